// round 10
// baseline (speedup 1.0000x reference)
#include <cuda_runtime.h>

// ---------------------------------------------------------------------------
// Pose2Mesh fully-collapsed linear implementation — SINGLE fused kernel.
// Phases chained by device-side flags (producers release via threadfence +
// atomic counter; consumers spin with nanosleep). Block roles by blockIdx.x:
//   [0, 320)      fold GEMM split-K partials (5 col-tiles x 64 k-splits)
//   [320, 368)    per-(joint, side) 3x3 M / bias dots
//   [368, 426)    finalize: reduce partials, fold neighbor+root terms -> W', b'
//   [426, ...)    main GEMM: out(B,151) = x(B,57) @ W' + b'
// Wave-1 blocks are scheduled in bid order and residency (>1100 blocks)
// exceeds the 426 upstream blocks, so all producers run in wave 1 -> no
// deadlock. Counters self-reset (last-block-out) -> graph-replay safe.
// ---------------------------------------------------------------------------

#define D_DIM   2048
#define NC      57      // J*3
#define NK      151
#define NKPAD   160
#define KSPLIT  64
#define KCHUNK  32      // D_DIM / KSPLIT
#define H_DIM   512
#define CPB     16      // cols per block (main)
#define NSLICES 10      // 160/16
#define RPB     64      // rows per block (main)
#define TPB     128

#define NB_FOLD 320     // 5 * KSPLIT
#define NB_M    48
#define NB_FIN  58
#define NB_PRE  (NB_FOLD + NB_M)          // 368
#define B_FIN0  NB_PRE                    // 368
#define B_MAIN0 (NB_PRE + NB_FIN)         // 426

// scratch (allocation-free: __device__ globals)
__device__ float g_M1[24 * 9];
__device__ float g_M2[24 * 9];
__device__ float g_bp1[72];
__device__ float g_bp2[72];
__device__ float g_Wpart[KSPLIT * 58 * NKPAD];
__device__ float g_W[NC * NKPAD];
__device__ float g_b[NKPAD];

// phase flags (zero-initialized at module load; self-reset each launch)
__device__ int g_c1;     // producers done (target NB_PRE)
__device__ int g_c2;     // finalize done  (target NB_FIN)
__device__ int g_done;   // blocks retired (target gridDim.x)

// NEB1[j]*3 and NEB2[j]*3 (base offsets into the 57-float joint vector)
__constant__ int c_NB1[24] = {51,33,36,51,39,42,51,45,48,54,45,48,54,54,54,54,15,18,21,24,27,30,27,30};
__constant__ int c_NB2[24] = {54,51,51,54,33,36,54,39,42,51,39,42, 0,15,18, 0,54,54,15,18,21,24,21,24};

__device__ __forceinline__ float fetchB(int f, int col,
                                        const float* __restrict__ Wsh, const float* __restrict__ Wca,
                                        const float* __restrict__ Wph, const float* __restrict__ Wlf,
                                        const float* __restrict__ Rf)
{
    if (col < 10)  return Wsh[f * 10 + col];
    if (col < 13)  return Wca[f * 3  + (col - 10)];
    if (col < 59)  return Wph[f * 46 + (col - 13)];
    if (col < 79)  return Wlf[f * 20 + (col - 59)];
    int t = col - 79;
    int j = t / 3, o = t - j * 3;
    return Rf[(j * D_DIM + f) * 3 + o];
}

// shared-memory overlay for the different block roles
union __align__(16) SMem {
    struct {
        float As[64][KCHUNK + 1];
        float Bs[KCHUNK][36];
    } fold;                                     // 13056 B
    struct {
        float sLw[3 * H_DIM];
        float sR [H_DIM * 3];
        float sLb[H_DIM];
    } mp;                                       // 14336 B
    struct {
        float  Xs[RPB * NC];                    // 14592 B
        float4 Ws4[NC][CPB / 4];                //  3648 B
        float  bias[CPB];
        float  Os[RPB * CPB];                   //  4096 B
    } mn;                                       // ~22.4 KB
};

__device__ __forceinline__ void spin_ge(volatile int* p, int target) {
    while (*p < target) __nanosleep(128);
}

__global__ void __launch_bounds__(TPB)
fused_kernel(const float* __restrict__ joints,
             const float* __restrict__ W_enc, const float* __restrict__ b_enc,
             const float* __restrict__ W_shape, const float* __restrict__ W_cam,
             const float* __restrict__ W_phi,   const float* __restrict__ W_leaf,
             const float* __restrict__ Rf,
             const float* __restrict__ L1_w, const float* __restrict__ L1_b,
             const float* __restrict__ L2_w, const float* __restrict__ L2_b,
             const float* __restrict__ R1,   const float* __restrict__ R2,
             const float* __restrict__ b_shape, const float* __restrict__ b_cam,
             const float* __restrict__ b_phi,   const float* __restrict__ b_leaf,
             const float* __restrict__ init_shape, const float* __restrict__ init_cam,
             const float* __restrict__ reg_b,
             float* __restrict__ out, int B)
{
    __shared__ SMem sm;
    const int bx  = blockIdx.x;
    const int tid = threadIdx.x;

    if (bx < NB_FOLD) {
        // ================= fold GEMM: split-K partials =================
        int ct = bx % 5;
        int ks = bx / 5;
        int kbase = ks * KCHUNK;

        // A loads: 464 float4 (58 rows x 8), 128 thr -> 4 guarded
        float4 va[4]; int vr[4], vq[4];
        #pragma unroll
        for (int i = 0; i < 4; i++) {
            int idx = tid + TPB * i;
            int r = idx >> 3, q = idx & 7;
            vr[i] = r; vq[i] = q;
            float4 v4 = make_float4(0.f, 0.f, 0.f, 0.f);
            if (idx < 464) {
                if (r < NC)       v4 = *(const float4*)(W_enc + r * D_DIM + kbase + q * 4);
                else if (r == NC) v4 = *(const float4*)(b_enc + kbase + q * 4);
            }
            va[i] = v4;
        }
        // B loads: 1024 scalars -> 8 each (gathered)
        float vb[8];
        #pragma unroll
        for (int i = 0; i < 8; i++) {
            int idx = tid + TPB * i;
            int kk = idx >> 5, cl = idx & 31;
            int gcol = ct * 32 + cl;
            vb[i] = (gcol < NK) ? fetchB(kbase + kk, gcol, W_shape, W_cam, W_phi, W_leaf, Rf) : 0.f;
        }
        #pragma unroll
        for (int i = 0; i < 4; i++) {
            int idx = tid + TPB * i;
            if (idx < 464 && vr[i] < 64) {
                float* dst = &sm.fold.As[vr[i]][vq[i] * 4];
                dst[0] = va[i].x; dst[1] = va[i].y; dst[2] = va[i].z; dst[3] = va[i].w;
            }
        }
        #pragma unroll
        for (int i = 0; i < 8; i++) {
            int idx = tid + TPB * i;
            sm.fold.Bs[idx >> 5][idx & 31] = vb[i];
        }
        __syncthreads();

        // compute: thread = (row r 0..63, col group cg of 16)
        int r  = tid >> 1;
        int cg = tid & 1;
        float acc[16];
        #pragma unroll
        for (int e = 0; e < 16; e++) acc[e] = 0.f;
        #pragma unroll
        for (int kk = 0; kk < KCHUNK; kk++) {
            float xc = sm.fold.As[r][kk];
            const float* bp = &sm.fold.Bs[kk][cg * 16];
            float4 w0 = *(const float4*)(bp);
            float4 w1 = *(const float4*)(bp + 4);
            float4 w2 = *(const float4*)(bp + 8);
            float4 w3 = *(const float4*)(bp + 12);
            acc[0]  = fmaf(xc, w0.x, acc[0]);  acc[1]  = fmaf(xc, w0.y, acc[1]);
            acc[2]  = fmaf(xc, w0.z, acc[2]);  acc[3]  = fmaf(xc, w0.w, acc[3]);
            acc[4]  = fmaf(xc, w1.x, acc[4]);  acc[5]  = fmaf(xc, w1.y, acc[5]);
            acc[6]  = fmaf(xc, w1.z, acc[6]);  acc[7]  = fmaf(xc, w1.w, acc[7]);
            acc[8]  = fmaf(xc, w2.x, acc[8]);  acc[9]  = fmaf(xc, w2.y, acc[9]);
            acc[10] = fmaf(xc, w2.z, acc[10]); acc[11] = fmaf(xc, w2.w, acc[11]);
            acc[12] = fmaf(xc, w3.x, acc[12]); acc[13] = fmaf(xc, w3.y, acc[13]);
            acc[14] = fmaf(xc, w3.z, acc[14]); acc[15] = fmaf(xc, w3.w, acc[15]);
        }
        if (r < 58) {
            float* dst = &g_Wpart[(ks * 58 + r) * NKPAD + ct * 32 + cg * 16];
            #pragma unroll
            for (int e = 0; e < 4; e++)
                *(float4*)(dst + e * 4) = make_float4(acc[e*4], acc[e*4+1], acc[e*4+2], acc[e*4+3]);
        }
        __syncthreads();
        __threadfence();
        if (tid == 0) atomicAdd(&g_c1, 1);
    }
    else if (bx < NB_PRE) {
        // ================= M-part: per-(joint, side) dots =================
        int mb = bx - NB_FOLD;            // 0..47
        int j  = mb >> 1;
        int s  = mb & 1;
        const float* Lw = (s ? L2_w : L1_w) + j * 3 * H_DIM;
        const float* Lb = (s ? L2_b : L1_b) + j * H_DIM;
        const float* Rm = (s ? R2   : R1  ) + j * H_DIM * 3;

        // 896 float4: 384 Lw + 384 R + 128 Lb; 7 per thread (exact)
        float4 v[7];
        #pragma unroll
        for (int i = 0; i < 7; i++) {
            int idx = tid + TPB * i;
            if      (idx < 384) v[i] = *(const float4*)(Lw + idx * 4);
            else if (idx < 768) v[i] = *(const float4*)(Rm + (idx - 384) * 4);
            else                v[i] = *(const float4*)(Lb + (idx - 768) * 4);
        }
        #pragma unroll
        for (int i = 0; i < 7; i++) {
            int idx = tid + TPB * i;
            if      (idx < 384) *(float4*)(sm.mp.sLw + idx * 4)         = v[i];
            else if (idx < 768) *(float4*)(sm.mp.sR  + (idx - 384) * 4) = v[i];
            else                *(float4*)(sm.mp.sLb + (idx - 768) * 4) = v[i];
        }
        __syncthreads();

        int lane = tid & 31;
        int w    = tid >> 5;              // 0..3
        for (int t = w; t < 12; t += 4) {
            int c = (t < 9) ? (t / 3) : 0;
            int o = (t < 9) ? (t % 3) : (t - 9);
            const float* ap = (t < 9) ? (sm.mp.sLw + c * H_DIM) : sm.mp.sLb;
            float sum = 0.f;
            #pragma unroll
            for (int i = 0; i < 16; i++) {
                int h = lane + 32 * i;
                sum = fmaf(ap[h], sm.mp.sR[h * 3 + o], sum);
            }
            #pragma unroll
            for (int d = 16; d > 0; d >>= 1) sum += __shfl_xor_sync(0xffffffffu, sum, d);
            if (lane == 0) {
                if (t < 9) { if (s) g_M2[j * 9 + t] = sum; else g_M1[j * 9 + t] = sum; }
                else       { if (s) g_bp2[j * 3 + o] = sum; else g_bp1[j * 3 + o] = sum; }
            }
        }
        __syncthreads();
        __threadfence();
        if (tid == 0) atomicAdd(&g_c1, 1);
    }
    else if (bx < B_MAIN0) {
        // ================= finalize =================
        if (tid == 0) spin_ge(&g_c1, NB_PRE);
        __syncthreads();
        __threadfence();

        int row = bx - B_FIN0;            // 0..57
        for (int col = tid; col < NKPAD; col += TPB) {
            float s = 0.f;
            #pragma unroll
            for (int p = 0; p < KSPLIT; p++) s += g_Wpart[(p * 58 + row) * NKPAD + col];

            bool isPose = (col >= 79 && col < NK);
            int t = 0, j = 0, o = 0;
            float s0 = 0.f;
            if (isPose) {
                t = col - 79; j = t / 3; o = t - 3 * j;
                #pragma unroll
                for (int p = 0; p < KSPLIT; p++) s0 += g_Wpart[(p * 58 + row) * NKPAD + 79 + o];
            }

            if (row < NC) {
                float w;
                if (col >= NK) {
                    w = 0.f;
                } else if (!isPose) {
                    w = s;
                } else {
                    w = s - s0;
                    int a1 = c_NB1[j], a2 = c_NB2[j];
                    if (row >= a1 && row < a1 + 3) w += g_M1[j * 9 + (row - a1) * 3 + o];
                    if (row >= a2 && row < a2 + 3) w += g_M2[j * 9 + (row - a2) * 3 + o];
                    if (row >= 51 && row < 54) w -= g_M1[(row - 51) * 3 + o];
                    if (row >= 54 && row < 57) w -= g_M2[(row - 54) * 3 + o];
                }
                g_W[row * NKPAD + col] = w;
            } else {
                float bv;
                if      (col >= NK) bv = 0.f;
                else if (col < 10)  bv = s + b_shape[col] + init_shape[col];
                else if (col < 13)  bv = s + b_cam[col - 10] + init_cam[col - 10];
                else if (col < 59)  bv = s + b_phi[col - 13];
                else if (col < 79)  bv = s + b_leaf[col - 59];
                else {
                    float bt = s  + reg_b[t] + g_bp1[t] + g_bp2[t];
                    float b0 = s0 + reg_b[o] + g_bp1[o] + g_bp2[o];
                    bv = bt - b0;
                }
                g_b[col] = bv;
            }
        }
        __syncthreads();
        __threadfence();
        if (tid == 0) atomicAdd(&g_c2, 1);
    }
    else {
        // ================= main GEMM =================
        int mb = bx - B_MAIN0;
        int nrowb = (B + RPB - 1) / RPB;
        int rb = (mb % nrowb) * RPB;
        int k0 = (mb / nrowb) * CPB;

        const int CAM_OFF   = B * 72;
        const int PHI_OFF   = CAM_OFF + B * 3;
        const int LEAF_OFF  = PHI_OFF + B * 46;
        const int SHAPE_OFF = LEAF_OFF + B * 20;

        // ---- stage X first (independent of upstream) ----
        if (rb + RPB <= B) {
            const float4* jp = (const float4*)(joints + rb * NC);
            float4 xv[8];
            #pragma unroll
            for (int i = 0; i < 8; i++) {
                int idx = tid + TPB * i;
                if (idx < 912) xv[i] = jp[idx];
            }
            #pragma unroll
            for (int i = 0; i < 8; i++) {
                int idx = tid + TPB * i;
                if (idx < 912) ((float4*)sm.mn.Xs)[idx] = xv[i];
            }
        } else {
            int nr = B - rb;
            for (int idx = tid; idx < nr * NC; idx += TPB)
                sm.mn.Xs[idx] = joints[rb * NC + idx];
        }

        // ---- wait for finalize, then stage W', b' ----
        if (tid == 0) spin_ge(&g_c2, NB_FIN);
        __syncthreads();
        __threadfence();

        {
            float4 wv[2];
            #pragma unroll
            for (int i = 0; i < 2; i++) {
                int idx = tid + TPB * i;
                if (idx < 228) {
                    int r = idx >> 2, q = idx & 3;
                    wv[i] = *(const float4*)(g_W + r * NKPAD + k0 + q * 4);
                }
            }
            #pragma unroll
            for (int i = 0; i < 2; i++) {
                int idx = tid + TPB * i;
                if (idx < 228) {
                    int r = idx >> 2, q = idx & 3;
                    sm.mn.Ws4[r][q] = wv[i];
                }
            }
        }
        if (tid < CPB) sm.mn.bias[tid] = g_b[k0 + tid];
        __syncthreads();

        const int ty = tid >> 1;
        const int tx = tid & 1;
        {
            float4 a0 = make_float4(sm.mn.bias[tx * 8 + 0], sm.mn.bias[tx * 8 + 1],
                                    sm.mn.bias[tx * 8 + 2], sm.mn.bias[tx * 8 + 3]);
            float4 a1 = make_float4(sm.mn.bias[tx * 8 + 4], sm.mn.bias[tx * 8 + 5],
                                    sm.mn.bias[tx * 8 + 6], sm.mn.bias[tx * 8 + 7]);

            const float* xrow = &sm.mn.Xs[ty * NC];
            #pragma unroll
            for (int c = 0; c < NC; c++) {
                float  xc = xrow[c];
                float4 w0 = sm.mn.Ws4[c][tx * 2];
                float4 w1 = sm.mn.Ws4[c][tx * 2 + 1];
                a0.x = fmaf(xc, w0.x, a0.x); a0.y = fmaf(xc, w0.y, a0.y);
                a0.z = fmaf(xc, w0.z, a0.z); a0.w = fmaf(xc, w0.w, a0.w);
                a1.x = fmaf(xc, w1.x, a1.x); a1.y = fmaf(xc, w1.y, a1.y);
                a1.z = fmaf(xc, w1.z, a1.z); a1.w = fmaf(xc, w1.w, a1.w);
            }
            float4* op = (float4*)&sm.mn.Os[ty * CPB + tx * 8];
            op[0] = a0;
            op[1] = a1;
        }
        __syncthreads();

        #pragma unroll
        for (int i = 0; i < 8; i++) {
            int idx = tid + TPB * i;
            int e = idx & (CPB - 1);
            int r = idx >> 4;
            int k = k0 + e;
            int b = rb + r;
            if (k < NK && b < B) {
                float val = sm.mn.Os[idx];
                if      (k < 10) out[SHAPE_OFF + b * 10 + k]        = val;
                else if (k < 13) out[CAM_OFF   + b * 3  + (k - 10)] = val;
                else if (k < 59) out[PHI_OFF   + b * 46 + (k - 13)] = val;
                else if (k < 79) out[LEAF_OFF  + b * 20 + (k - 59)] = val;
                else             out[b * 72 + (k - 79)]             = val;
            }
        }
    }

    // ---- last-block-out counter reset (graph-replay safe) ----
    __threadfence();
    if (tid == 0) {
        int old = atomicAdd(&g_done, 1);
        if (old == (int)gridDim.x - 1) {
            g_c1 = 0;
            g_c2 = 0;
            __threadfence();
            g_done = 0;
        }
    }
}

// ---------------------------------------------------------------------------
extern "C" void kernel_launch(void* const* d_in, const int* in_sizes, int n_in,
                              void* d_out, int out_size)
{
    const float* joints     = (const float*)d_in[0];
    const float* W_enc      = (const float*)d_in[1];
    const float* b_enc      = (const float*)d_in[2];
    const float* W_shape    = (const float*)d_in[3];
    const float* b_shape    = (const float*)d_in[4];
    const float* W_cam      = (const float*)d_in[5];
    const float* b_cam      = (const float*)d_in[6];
    const float* W_phi      = (const float*)d_in[7];
    const float* b_phi      = (const float*)d_in[8];
    const float* W_leaf     = (const float*)d_in[9];
    const float* b_leaf     = (const float*)d_in[10];
    const float* init_shape = (const float*)d_in[11];
    const float* init_cam   = (const float*)d_in[12];
    const float* L1_w       = (const float*)d_in[13];
    const float* L1_b       = (const float*)d_in[14];
    const float* L2_w       = (const float*)d_in[15];
    const float* L2_b       = (const float*)d_in[16];
    const float* Rf         = (const float*)d_in[17];
    const float* R1         = (const float*)d_in[18];
    const float* R2         = (const float*)d_in[19];
    const float* reg_b      = (const float*)d_in[20];

    int B = in_sizes[0] / NC;
    int nrowb = (B + RPB - 1) / RPB;
    int grid = B_MAIN0 + nrowb * NSLICES;

    fused_kernel<<<grid, TPB>>>(joints,
                                W_enc, b_enc, W_shape, W_cam, W_phi, W_leaf, Rf,
                                L1_w, L1_b, L2_w, L2_b, R1, R2,
                                b_shape, b_cam, b_phi, b_leaf, init_shape, init_cam, reg_b,
                                (float*)d_out, B);
}